// round 1
// baseline (speedup 1.0000x reference)
#include <cuda_runtime.h>

// ---------------- problem constants ----------------
// x:(32,3,128,128)  enc1->(32,128,64,64)  enc2->(32,128,32,32) pool->(32,128,8,8)
// proj-> z_e (32,64,8,8)  VQ K=512,D=64  dproj->(32,128,8,8) up x16 -> dconv1 -> dconv2 -> (32,3,128,128)

// ---------------- device scratch (no allocations allowed) ----------------
__device__ float g_h1[32 * 128 * 64 * 64];    // encoder conv1 output (64 MB)
__device__ float g_hp[32 * 128 * 8 * 8];      // pooled encoder features
__device__ float g_y [32 * 128 * 8 * 8];      // dproj output (relu'd), block-constant decoder state
__device__ float g_r9[32 * 9 * 128 * 64];     // dconv1: 9 distinct values per 16x16 block, relu'd
__device__ float g_w25[25 * 128 * 128];       // pre-summed dconv1 weight subsets, layout [m][ic][oc]
__device__ int   g_idx[2048];
__device__ float g_loss;

// ================= encoder conv1: 3->128, 3x3, stride 2, pad 1, relu =================
// grid (64 oy, 32 b), 256 thr: ox = tid&63, ocg = tid>>6 (4 groups of 32 oc)
__global__ void enc1_kernel(const float* __restrict__ x,
                            const float* __restrict__ w,
                            const float* __restrict__ bias) {
    __shared__ float ws[3456]; // [c][ky][kx][128]
    int oy = blockIdx.x, b = blockIdx.y;
    int tid = threadIdx.x;
    for (int e = tid; e < 3456; e += 256) {
        int oc = e & 127; int t = e >> 7;
        int c = t / 9; int r = t - c * 9; int ky = r / 3, kx = r - ky * 3;
        ws[e] = w[((oc * 3 + c) * 3 + ky) * 3 + kx];
    }
    __syncthreads();
    int ox = tid & 63, ocg = tid >> 6;
    float acc[32];
#pragma unroll
    for (int i = 0; i < 32; i++) acc[i] = __ldg(bias + ocg * 32 + i);
    const float* xb = x + b * 3 * 128 * 128;
#pragma unroll
    for (int c = 0; c < 3; c++) {
#pragma unroll
        for (int ky = 0; ky < 3; ky++) {
            int iy = 2 * oy + ky - 1;
#pragma unroll
            for (int kx = 0; kx < 3; kx++) {
                int ix = 2 * ox + kx - 1;
                float xv = 0.f;
                if ((unsigned)iy < 128u && (unsigned)ix < 128u)
                    xv = __ldg(xb + (c * 128 + iy) * 128 + ix);
                const float* wp = &ws[((c * 3 + ky) * 3 + kx) * 128 + ocg * 32];
#pragma unroll
                for (int q = 0; q < 8; q++) {
                    float4 wv = *(const float4*)(wp + q * 4);
                    acc[q * 4 + 0] += wv.x * xv;
                    acc[q * 4 + 1] += wv.y * xv;
                    acc[q * 4 + 2] += wv.z * xv;
                    acc[q * 4 + 3] += wv.w * xv;
                }
            }
        }
    }
    float* op = g_h1 + ((b * 128 + ocg * 32) * 64 + oy) * 64 + ox;
#pragma unroll
    for (int i = 0; i < 32; i++) op[i * 64 * 64] = fmaxf(acc[i], 0.f);
}

// ================= encoder conv2 (128->128, 3x3, s2, p1) + relu + 4x4 avg pool (fused) =================
// grid (32 b, 4 ocg, 8 gy), 256 thr. Block computes 32 oc x (4 rows x 32 cols) outputs
// then pools the 4x4 blocks -> writes g_hp[b][oc][gy][0..7].
__global__ void enc2_pool_kernel(const float* __restrict__ w,
                                 const float* __restrict__ bias) {
    __shared__ float sm[7056];
    float* s_in = sm;          // 8 ic x 9 rows x 66 cols = 4752
    float* s_w  = sm + 4752;   // 8 ic x 9 taps x 32 oc  = 2304
    int b = blockIdx.x, ocg = blockIdx.y, gy = blockIdx.z;
    int tid = threadIdx.x;
    int ox = tid & 31, ocq = tid >> 5; // ocq 0..7, thread owns 4 oc = ocq*4..+3, 4 rows
    float acc[4][4];
#pragma unroll
    for (int r = 0; r < 4; r++)
#pragma unroll
        for (int i = 0; i < 4; i++) acc[r][i] = __ldg(bias + ocg * 32 + ocq * 4 + i);

    for (int ch = 0; ch < 16; ch++) {
        __syncthreads();
        for (int e = tid; e < 4752; e += 256) {
            int ic = e / 594; int rem = e - ic * 594;
            int rr = rem / 66; int cc = rem - rr * 66;
            int iy = gy * 8 - 1 + rr; int ix = cc - 1;
            float v = 0.f;
            if ((unsigned)iy < 64u && (unsigned)ix < 64u)
                v = g_h1[((b * 128 + ch * 8 + ic) * 64 + iy) * 64 + ix];
            s_in[e] = v;
        }
        for (int e = tid; e < 2304; e += 256) {
            int ic = e / 288; int rem = e - ic * 288;
            int t = rem >> 5; int ocl = rem & 31;
            int ky = t / 3, kx = t - ky * 3;
            s_w[e] = __ldg(w + (((ocg * 32 + ocl) * 128 + ch * 8 + ic) * 3 + ky) * 3 + kx);
        }
        __syncthreads();
#pragma unroll 2
        for (int ic = 0; ic < 8; ic++) {
            const float* sib = s_in + ic * 594 + 2 * ox;
            const float* swb = s_w + ic * 288 + ocq * 4;
#pragma unroll
            for (int ky = 0; ky < 3; ky++) {
#pragma unroll
                for (int kx = 0; kx < 3; kx++) {
                    float4 wv = *(const float4*)(swb + (ky * 3 + kx) * 32);
                    float iv[4];
#pragma unroll
                    for (int r = 0; r < 4; r++) iv[r] = sib[(2 * r + ky) * 66 + kx];
#pragma unroll
                    for (int r = 0; r < 4; r++) {
                        acc[r][0] += wv.x * iv[r];
                        acc[r][1] += wv.y * iv[r];
                        acc[r][2] += wv.z * iv[r];
                        acc[r][3] += wv.w * iv[r];
                    }
                }
            }
        }
    }
    // relu + pool (4 rows reduced in regs, 4 cols via shared)
    __syncthreads();
    float* s_red = sm; // 32 oc x 33
#pragma unroll
    for (int i = 0; i < 4; i++) {
        float s = 0.f;
#pragma unroll
        for (int r = 0; r < 4; r++) s += fmaxf(acc[r][i], 0.f);
        s_red[(ocq * 4 + i) * 33 + ox] = s;
    }
    __syncthreads();
    {
        int oc = tid & 31, gxp = tid >> 5;
        float s = 0.f;
#pragma unroll
        for (int j = 0; j < 4; j++) s += s_red[oc * 33 + gxp * 4 + j];
        g_hp[((b * 128 + ocg * 32 + oc) * 8 + gy) * 8 + gxp] = s * (1.f / 16.f);
    }
}

// ================= proj 1x1: 128 -> 64, writes z_e straight into d_out slot =================
__global__ void proj_kernel(const float* __restrict__ w,
                            const float* __restrict__ bias,
                            float* __restrict__ zout) {
    __shared__ float s_hp[8192]; // [hc][pos]
    int b = blockIdx.x, tid = threadIdx.x;
    for (int e = tid; e < 8192; e += 256) s_hp[e] = g_hp[b * 8192 + e];
    __syncthreads();
    int pos = tid & 63, dg = tid >> 6;
    for (int dl = 0; dl < 16; dl++) {
        int d = dg * 16 + dl;
        float acc = __ldg(bias + d);
        const float* wr = w + d * 128;
#pragma unroll 8
        for (int hc = 0; hc < 128; hc++) acc += __ldg(wr + hc) * s_hp[hc * 64 + pos];
        zout[(b * 64 + d) * 64 + pos] = acc;
    }
}

// ================= vector quantizer: argmin over 512 codes + loss partial =================
__global__ void zero_loss_kernel() { g_loss = 0.f; }

__global__ void vq_kernel(const float* __restrict__ z,  // z_e in d_out, layout [b][d][pos]
                          const float* __restrict__ cb,
                          float* __restrict__ idx_out) {
    __shared__ float s_z[64];
    __shared__ float sv[128];
    __shared__ int   si[128];
    int n = blockIdx.x; int b = n >> 6, pos = n & 63;
    int tid = threadIdx.x;
    if (tid < 64) s_z[tid] = z[(b * 64 + tid) * 64 + pos];
    __syncthreads();
    float bestv = 3.4e38f; int besti = 0;
    for (int kk = 0; kk < 4; kk++) {
        int k = tid * 4 + kk;
        const float* cr = cb + k * 64;
        float s = 0.f;
#pragma unroll 8
        for (int d = 0; d < 64; d++) { float df = s_z[d] - __ldg(cr + d); s += df * df; }
        if (s < bestv) { bestv = s; besti = k; }
    }
    sv[tid] = bestv; si[tid] = besti;
    __syncthreads();
    for (int st = 64; st > 0; st >>= 1) {
        if (tid < st) {
            float v2 = sv[tid + st]; int i2 = si[tid + st];
            if (v2 < sv[tid] || (v2 == sv[tid] && i2 < si[tid])) { sv[tid] = v2; si[tid] = i2; }
        }
        __syncthreads();
    }
    if (tid == 0) {
        g_idx[n] = si[0];
        idx_out[n] = (float)si[0];
        atomicAdd(&g_loss, sv[0]);
    }
}

__global__ void finalize_loss_kernel(float* __restrict__ out) {
    // vq_loss = (1 + 0.25) * mean((z_q - z_e)^2) ; mean over 2048*64 elements
    out[0] = g_loss * (1.25f / 131072.f);
}

// ================= dproj 1x1: 64 -> 128 on quantized codes, relu (pre-upsample) =================
__global__ void dproj_kernel(const float* __restrict__ cb,
                             const float* __restrict__ w,
                             const float* __restrict__ bias) {
    __shared__ float s_zq[4096]; // [d][pos]
    __shared__ int   s_i[64];
    int b = blockIdx.x, tid = threadIdx.x;
    if (tid < 64) s_i[tid] = g_idx[b * 64 + tid];
    __syncthreads();
    for (int e = tid; e < 4096; e += 256) {
        int d = e >> 6, pos = e & 63;
        s_zq[e] = __ldg(cb + s_i[pos] * 64 + d);
    }
    __syncthreads();
    int pos = tid & 63, hg = tid >> 6;
    for (int h = 0; h < 32; h++) {
        int hc = hg * 32 + h;
        float acc = __ldg(bias + hc);
        const float* wr = w + hc * 64;
#pragma unroll 8
        for (int d = 0; d < 64; d++) acc += __ldg(wr + d) * s_zq[d * 64 + pos];
        g_y[b * 8192 + hc * 64 + pos] = fmaxf(acc, 0.f); // relu(upsample(y)) == upsample(relu(y))
    }
}

// ================= dconv1 weight-subset precompute: 25 matrices [m][ic][oc] =================
// subset index: 0:{0} 1:{2} 2:{0,1} 3:{1,2} 4:{0,1,2};  m = sy*5 + sx
__global__ void w25_kernel(const float* __restrict__ w) {
    int g = blockIdx.x * 256 + threadIdx.x;
    if (g >= 25 * 16384) return;
    int m = g >> 14; int r = g & 16383; int ic = r & 127; int oc = r >> 7;
    int sy = m / 5, sx = m - sy * 5;
    const int mask[5] = {1, 4, 3, 6, 7};
    float s = 0.f;
    for (int j = 0; j < 3; j++) if ((mask[sy] >> j) & 1)
        for (int i = 0; i < 3; i++) if ((mask[sx] >> i) & 1)
            s += __ldg(w + ((oc * 128 + ic) * 3 + j) * 3 + i);
    g_w25[(m * 128 + ic) * 128 + oc] = s;
}

// ================= dconv1 on block-constant input: 9 distinct values per 16x16 block =================
// grid (32 b, 9 vt), 256 thr. vt = ty*3+tx, ty/tx in {top,mid,bot}/{left,mid,right}.
__global__ void dconv1_blocks_kernel(const float* __restrict__ bias) {
    __shared__ float s_y[8192]; // [ic][pos]
    int b = blockIdx.x, vt = blockIdx.y;
    int tid = threadIdx.x;
    for (int e = tid; e < 8192; e += 256) s_y[e] = g_y[b * 8192 + e];
    __syncthreads();

    int lane = tid & 31;
    int ocb = (tid >> 5) * 16;
    int ty = vt / 3, tx = vt - ty * 3;

    int nyp, ys[2], ydy[2];
    if (ty == 0)      { nyp = 2; ys[0] = 0; ydy[0] = -1; ys[1] = 3; ydy[1] = 0; }
    else if (ty == 1) { nyp = 1; ys[0] = 4; ydy[0] = 0;  ys[1] = 0; ydy[1] = 0; }
    else              { nyp = 2; ys[0] = 2; ydy[0] = 0;  ys[1] = 1; ydy[1] = 1; }
    int nxp, xs[2], xdx[2];
    if (tx == 0)      { nxp = 2; xs[0] = 0; xdx[0] = -1; xs[1] = 3; xdx[1] = 0; }
    else if (tx == 1) { nxp = 1; xs[0] = 4; xdx[0] = 0;  xs[1] = 0; xdx[1] = 0; }
    else              { nxp = 2; xs[0] = 2; xdx[0] = 0;  xs[1] = 1; xdx[1] = 1; }

    float acc0[16], acc1[16];
#pragma unroll
    for (int i = 0; i < 16; i++) { acc0[i] = __ldg(bias + ocb + i); acc1[i] = acc0[i]; }

    int pos0 = lane, pos1 = lane + 32;
    int gy0 = pos0 >> 3, gx0 = pos0 & 7;
    int gy1 = pos1 >> 3, gx1 = pos1 & 7;

    for (int a = 0; a < nyp; a++) {
        for (int c = 0; c < nxp; c++) {
            int m = ys[a] * 5 + xs[c];
            int dy = ydy[a], dx = xdx[c];
            int ny0 = gy0 + dy, nx0 = gx0 + dx;
            int ny1 = gy1 + dy, nx1 = gx1 + dx;
            bool v0 = ((unsigned)ny0 < 8u) && ((unsigned)nx0 < 8u);
            bool v1 = ((unsigned)ny1 < 8u) && ((unsigned)nx1 < 8u);
            int np0 = ny0 * 8 + nx0, np1 = ny1 * 8 + nx1;
            const float* wbase = g_w25 + (m * 128) * 128 + ocb;
#pragma unroll 4
            for (int ic = 0; ic < 128; ic++) {
                float yv0 = v0 ? s_y[ic * 64 + np0] : 0.f;
                float yv1 = v1 ? s_y[ic * 64 + np1] : 0.f;
                const float* wp = wbase + ic * 128;
#pragma unroll
                for (int q = 0; q < 4; q++) {
                    float4 wv = __ldg((const float4*)wp + q);
                    acc0[q * 4 + 0] += wv.x * yv0; acc1[q * 4 + 0] += wv.x * yv1;
                    acc0[q * 4 + 1] += wv.y * yv0; acc1[q * 4 + 1] += wv.y * yv1;
                    acc0[q * 4 + 2] += wv.z * yv0; acc1[q * 4 + 2] += wv.z * yv1;
                    acc0[q * 4 + 3] += wv.w * yv0; acc1[q * 4 + 3] += wv.w * yv1;
                }
            }
        }
    }
    float* op = g_r9 + ((size_t)(b * 9 + vt) * 128 + ocb) * 64;
#pragma unroll
    for (int i = 0; i < 16; i++) {
        op[i * 64 + pos0] = fmaxf(acc0[i], 0.f);
        op[i * 64 + pos1] = fmaxf(acc1[i], 0.f);
    }
}

// ================= dconv2 1x1 (128->3) on 9 block values + scatter to full image =================
// grid (64 pos, 32 b), 128 thr
__global__ void dconv2_scatter_kernel(const float* __restrict__ w,
                                      const float* __restrict__ bias,
                                      float* __restrict__ xhat) {
    __shared__ float s_r[1152]; // [vt][oc]
    __shared__ float s_v[27];   // [vt][co]
    int pos = blockIdx.x, b = blockIdx.y;
    int tid = threadIdx.x;
    for (int e = tid; e < 1152; e += 128) {
        int vt = e >> 7, oc = e & 127;
        s_r[e] = g_r9[((size_t)(b * 9 + vt) * 128 + oc) * 64 + pos];
    }
    __syncthreads();
    if (tid < 27) {
        int vt = tid / 3, co = tid - vt * 3;
        float acc = __ldg(bias + co);
        const float* wr = w + co * 128;
        const float* rr = s_r + vt * 128;
#pragma unroll 8
        for (int oc = 0; oc < 128; oc++) acc += __ldg(wr + oc) * rr[oc];
        s_v[tid] = acc;
    }
    __syncthreads();
    int gy = pos >> 3, gx = pos & 7;
    for (int pp = tid; pp < 256; pp += 128) {
        int ly = pp >> 4, lx = pp & 15;
        int ty2 = (ly == 0) ? 0 : ((ly == 15) ? 2 : 1);
        int tx2 = (lx == 0) ? 0 : ((lx == 15) ? 2 : 1);
        int vtp = ty2 * 3 + tx2;
        int py = gy * 16 + ly, px = gx * 16 + lx;
#pragma unroll
        for (int co = 0; co < 3; co++)
            xhat[((b * 3 + co) * 128 + py) * 128 + px] = s_v[vtp * 3 + co];
    }
}

// ================= launch =================
extern "C" void kernel_launch(void* const* d_in, const int* in_sizes, int n_in,
                              void* d_out, int out_size) {
    const float* x   = (const float*)d_in[0];
    const float* ew1 = (const float*)d_in[1];
    const float* eb1 = (const float*)d_in[2];
    const float* ew2 = (const float*)d_in[3];
    const float* eb2 = (const float*)d_in[4];
    const float* pw  = (const float*)d_in[5];
    const float* pb  = (const float*)d_in[6];
    const float* cb  = (const float*)d_in[7];
    const float* dpw = (const float*)d_in[8];
    const float* dpb = (const float*)d_in[9];
    const float* dw1 = (const float*)d_in[10];
    const float* db1 = (const float*)d_in[11];
    const float* dw2 = (const float*)d_in[12];
    const float* db2 = (const float*)d_in[13];

    float* out   = (float*)d_out;
    float* xhat  = out;               // 32*3*128*128 = 1572864
    float* idxo  = out + 1572864;     // 32*8*8       = 2048
    float* losso = out + 1574912;     // 1
    float* zeo   = out + 1574913;     // 32*64*8*8    = 131072

    enc1_kernel<<<dim3(64, 32), 256>>>(x, ew1, eb1);
    enc2_pool_kernel<<<dim3(32, 4, 8), 256>>>(ew2, eb2);
    proj_kernel<<<32, 256>>>(pw, pb, zeo);
    zero_loss_kernel<<<1, 1>>>();
    vq_kernel<<<2048, 128>>>(zeo, cb, idxo);
    finalize_loss_kernel<<<1, 1>>>(losso);
    w25_kernel<<<1600, 256>>>(dw1);
    dproj_kernel<<<32, 256>>>(cb, dpw, dpb);
    dconv1_blocks_kernel<<<dim3(32, 9), 256>>>(db1);
    dconv2_scatter_kernel<<<dim3(64, 32), 128>>>(dw2, db2, xhat);
}